// round 1
// baseline (speedup 1.0000x reference)
#include <cuda_runtime.h>
#include <cuda_bf16.h>
#include <math.h>

// Problem constants (fixed by the reference setup)
#define NSPK 512   // speakers
#define UU   32    // utterances per speaker
#define DD   512   // embedding dim
#define NU   (NSPK*UU)   // 16384 rows of E
#define EPS  1e-8f

#define BM 32      // rows of E per block
#define BK 16      // K chunk
#define TPB 256    // threads per block (8 warps: ty=tid>>5 in [0,8), tx=tid&31)

// Scratch (no cudaMalloc allowed)
__device__ float g_cent[NSPK * DD];   // centroids (1 MB)
__device__ float g_inv_c[NSPK];       // 1/||centroid||
__device__ float g_inv_e[NU];         // 1/||e_i||
__device__ float g_part[NU / BM];     // per-block partial sums (512)

// ---------------------------------------------------------------------------
// Kernel 1: per-speaker centroid + centroid inv-norm + per-utterance inv-norm
// grid = NSPK blocks, 256 threads
// ---------------------------------------------------------------------------
__global__ void centroid_kernel(const float* __restrict__ emb) {
    const int n = blockIdx.x;
    const int tid = threadIdx.x;
    const float* base = emb + (size_t)n * UU * DD;

    __shared__ float red[8];

    // centroid: each thread handles dims tid, tid+256 (coalesced per u-row)
    float sumsq = 0.f;
    #pragma unroll
    for (int d = tid; d < DD; d += TPB) {
        float s = 0.f;
        #pragma unroll
        for (int u = 0; u < UU; u++) s += base[u * DD + d];
        s *= (1.0f / UU);
        g_cent[n * DD + d] = s;
        sumsq += s * s;
    }
    // block-reduce sumsq
    #pragma unroll
    for (int o = 16; o > 0; o >>= 1)
        sumsq += __shfl_xor_sync(0xffffffffu, sumsq, o);
    const int warp = tid >> 5, lane = tid & 31;
    if (lane == 0) red[warp] = sumsq;
    __syncthreads();
    if (tid == 0) {
        float t = 0.f;
        #pragma unroll
        for (int i = 0; i < 8; i++) t += red[i];
        g_inv_c[n] = 1.0f / fmaxf(sqrtf(t), EPS);
    }

    // per-utterance norms: warp w handles rows u = w, w+8, w+16, w+24
    for (int u = warp; u < UU; u += 8) {
        float s = 0.f;
        #pragma unroll
        for (int d = lane; d < DD; d += 32) {
            float v = base[u * DD + d];
            s = fmaf(v, v, s);
        }
        #pragma unroll
        for (int o = 16; o > 0; o >>= 1)
            s += __shfl_xor_sync(0xffffffffu, s, o);
        if (lane == 0) g_inv_e[n * UU + u] = 1.0f / fmaxf(sqrtf(s), EPS);
    }
}

// ---------------------------------------------------------------------------
// Kernel 2: S = E(16384x512) @ C^T(512x512), fused scale + log-softmax row
// epilogue + diagonal pick. One block = 32 full rows (all 512 columns), so
// the softmax axis is block-local. One warp owns 4 complete rows.
// grid = NU/BM = 512 blocks, 256 threads
// ---------------------------------------------------------------------------
__global__ void gemm_loss_kernel(const float* __restrict__ E,
                                 const float* __restrict__ wp,
                                 const float* __restrict__ bp) {
    __shared__ float As[BK][BM + 1];    // +1 pad: conflict-free transposed STS
    __shared__ float Bs[BK][NSPK + 1];  // +1 pad: conflict-free transposed STS
    __shared__ float warp_sums[8];

    const int tid = threadIdx.x;
    const int tx = tid & 31;      // column lane
    const int ty = tid >> 5;      // warp id (row group)
    const int bi = blockIdx.x;
    const float* Eb = E + (size_t)bi * BM * DD;

    float acc[4][16];
    #pragma unroll
    for (int r = 0; r < 4; r++)
        #pragma unroll
        for (int j = 0; j < 16; j++) acc[r][j] = 0.f;

    for (int k0 = 0; k0 < DD; k0 += BK) {
        // ---- load A tile (32 rows x 16 k), transposed into As[k][row]
        if (tid < 128) {
            const int r = tid >> 2, kg = tid & 3;
            float4 v = *(const float4*)(Eb + r * DD + k0 + kg * 4);
            As[kg * 4 + 0][r] = v.x;
            As[kg * 4 + 1][r] = v.y;
            As[kg * 4 + 2][r] = v.z;
            As[kg * 4 + 3][r] = v.w;
        }
        // ---- load B tile (512 cols x 16 k), transposed into Bs[k][col]
        #pragma unroll
        for (int it = 0; it < 8; it++) {
            const int idx = tid + it * TPB;     // 0..2047
            const int j = idx >> 2, kg = idx & 3;
            float4 v = *(const float4*)(g_cent + j * DD + k0 + kg * 4);
            Bs[kg * 4 + 0][j] = v.x;
            Bs[kg * 4 + 1][j] = v.y;
            Bs[kg * 4 + 2][j] = v.z;
            Bs[kg * 4 + 3][j] = v.w;
        }
        __syncthreads();

        #pragma unroll
        for (int k = 0; k < BK; k++) {
            const float a0 = As[k][ty * 4 + 0];
            const float a1 = As[k][ty * 4 + 1];
            const float a2 = As[k][ty * 4 + 2];
            const float a3 = As[k][ty * 4 + 3];
            #pragma unroll
            for (int jj = 0; jj < 16; jj++) {
                const float bv = Bs[k][tx + 32 * jj];
                acc[0][jj] = fmaf(a0, bv, acc[0][jj]);
                acc[1][jj] = fmaf(a1, bv, acc[1][jj]);
                acc[2][jj] = fmaf(a2, bv, acc[2][jj]);
                acc[3][jj] = fmaf(a3, bv, acc[3][jj]);
            }
        }
        __syncthreads();
    }

    // ---- fused epilogue: scale -> log-softmax over 512 cols -> diag pick
    const float w = *wp, b = *bp;
    float invc[16];
    #pragma unroll
    for (int jj = 0; jj < 16; jj++) invc[jj] = g_inv_c[tx + 32 * jj];

    float local = 0.f;  // sum of diag log-probs for this warp's rows
    #pragma unroll
    for (int rr = 0; rr < 4; rr++) {
        const int r = ty * 4 + rr;
        const int gi = bi * BM + r;          // global row (n*U + u)
        const float ie = g_inv_e[gi];
        const float wie = w * ie;

        float m = -INFINITY;
        #pragma unroll
        for (int jj = 0; jj < 16; jj++) {
            const float v = fmaf(wie * invc[jj], acc[rr][jj], b);
            acc[rr][jj] = v;
            m = fmaxf(m, v);
        }
        #pragma unroll
        for (int o = 16; o > 0; o >>= 1)
            m = fmaxf(m, __shfl_xor_sync(0xffffffffu, m, o));

        float s = 0.f;
        #pragma unroll
        for (int jj = 0; jj < 16; jj++) s += expf(acc[rr][jj] - m);
        #pragma unroll
        for (int o = 16; o > 0; o >>= 1)
            s += __shfl_xor_sync(0xffffffffu, s, o);

        const float lse = m + logf(s);
        const int n = gi >> 5;               // speaker index = diag column
        if (tx == (n & 31)) local += acc[rr][n >> 5] - lse;
    }
    // warp-reduce the diag contributions (only owner lanes are non-zero)
    #pragma unroll
    for (int o = 16; o > 0; o >>= 1)
        local += __shfl_xor_sync(0xffffffffu, local, o);
    if (tx == 0) warp_sums[ty] = local;
    __syncthreads();
    if (tid == 0) {
        float t = 0.f;
        #pragma unroll
        for (int i = 0; i < 8; i++) t += warp_sums[i];
        g_part[bi] = t;
    }
}

// ---------------------------------------------------------------------------
// Kernel 3: deterministic final reduction -> loss = -sum / (N*U)
// ---------------------------------------------------------------------------
__global__ void finalize_kernel(float* __restrict__ out) {
    __shared__ float red[8];
    const int tid = threadIdx.x;
    float s = g_part[tid] + g_part[tid + 256];
    #pragma unroll
    for (int o = 16; o > 0; o >>= 1)
        s += __shfl_xor_sync(0xffffffffu, s, o);
    const int warp = tid >> 5, lane = tid & 31;
    if (lane == 0) red[warp] = s;
    __syncthreads();
    if (tid == 0) {
        float t = 0.f;
        #pragma unroll
        for (int i = 0; i < 8; i++) t += red[i];
        out[0] = -t * (1.0f / (float)NU);
    }
}

extern "C" void kernel_launch(void* const* d_in, const int* in_sizes, int n_in,
                              void* d_out, int out_size) {
    const float* emb = (const float*)d_in[0];
    const float* w = (const float*)d_in[1];
    const float* b = (const float*)d_in[2];
    float* out = (float*)d_out;

    centroid_kernel<<<NSPK, TPB>>>(emb);
    gemm_loss_kernel<<<NU / BM, TPB>>>(emb, w, b);
    finalize_kernel<<<1, 256>>>(out);
}

// round 5
// speedup vs baseline: 7.9273x; 7.9273x over previous
#include <cuda_runtime.h>
#include <cuda_bf16.h>
#include <cstdint>
#include <math.h>

#define NSPK 512
#define UU   32
#define DD   512
#define NU   (NSPK*UU)
#define EPS  1e-8f

// ---------------- device scratch (no cudaMalloc allowed) ----------------
__device__ __nv_bfloat16 g_Ebf[(size_t)NU * DD];   // normalized embeddings, bf16 (16 MB)
__device__ float         g_cent[NSPK * DD];        // raw centroids fp32 (1 MB)
__device__ __nv_bfloat16 g_Cbf[NSPK * DD];         // normalized centroids, bf16 (0.5 MB)
__device__ float         g_part[256];              // per-GEMM-block partial sums

// ---------------- PTX helpers (sm_80-class only: no tcgen05 on this target) ----
static __device__ __forceinline__ uint32_t smem_u32(const void* p) {
    uint32_t a;
    asm("{ .reg .u64 t; cvta.to.shared.u64 t, %1; cvt.u32.u64 %0, t; }" : "=r"(a) : "l"(p));
    return a;
}
static __device__ __forceinline__ void ldsm_x4(uint32_t& r0, uint32_t& r1,
                                               uint32_t& r2, uint32_t& r3, uint32_t addr) {
    asm volatile("ldmatrix.sync.aligned.m8n8.x4.shared.b16 {%0,%1,%2,%3}, [%4];"
                 : "=r"(r0), "=r"(r1), "=r"(r2), "=r"(r3) : "r"(addr));
}
static __device__ __forceinline__ void ldsm_x2(uint32_t& r0, uint32_t& r1, uint32_t addr) {
    asm volatile("ldmatrix.sync.aligned.m8n8.x2.shared.b16 {%0,%1}, [%2];"
                 : "=r"(r0), "=r"(r1) : "r"(addr));
}
static __device__ __forceinline__ void mma16816(float& d0, float& d1, float& d2, float& d3,
                                                uint32_t a0, uint32_t a1, uint32_t a2, uint32_t a3,
                                                uint32_t b0, uint32_t b1) {
    asm volatile(
        "mma.sync.aligned.m16n8k16.row.col.f32.bf16.bf16.f32 "
        "{%0,%1,%2,%3}, {%4,%5,%6,%7}, {%8,%9}, {%0,%1,%2,%3};"
        : "+f"(d0), "+f"(d1), "+f"(d2), "+f"(d3)
        : "r"(a0), "r"(a1), "r"(a2), "r"(a3), "r"(b0), "r"(b1));
}
static __device__ __forceinline__ void cpa16(uint32_t dst, const void* gsrc) {
    unsigned long long g = (unsigned long long)__cvta_generic_to_global(gsrc);
    asm volatile("cp.async.cg.shared.global [%0], [%1], 16;" :: "r"(dst), "l"(g));
}

// ---------------------------------------------------------------------------
// Kernel P: per-speaker pass: centroid (fp32) + per-row norms + bf16 rows
// grid = 512, 256 threads, 64KB dynamic smem
// ---------------------------------------------------------------------------
__global__ void __launch_bounds__(256, 1) prep_kernel(const float* __restrict__ emb) {
    extern __shared__ float s[];
    const int n = blockIdx.x, tid = threadIdx.x;

    const float4* src = reinterpret_cast<const float4*>(emb) + (size_t)n * 4096;
    float4* s4 = reinterpret_cast<float4*>(s);
    #pragma unroll
    for (int i = 0; i < 16; i++) s4[tid + i * 256] = src[tid + i * 256];
    __syncthreads();

    #pragma unroll
    for (int d = tid; d < DD; d += 256) {
        float sum = 0.f;
        #pragma unroll
        for (int u = 0; u < UU; u++) sum += s[u * DD + d];
        g_cent[n * DD + d] = sum * (1.0f / UU);
    }

    const int w = tid >> 5, lane = tid & 31;
    for (int u = w; u < UU; u += 8) {
        float v[16], ss = 0.f;
        #pragma unroll
        for (int j = 0; j < 16; j++) {
            v[j] = s[u * DD + lane + j * 32];
            ss = fmaf(v[j], v[j], ss);
        }
        #pragma unroll
        for (int o = 16; o > 0; o >>= 1) ss += __shfl_xor_sync(0xffffffffu, ss, o);
        const float inv = 1.0f / fmaxf(sqrtf(ss), EPS);
        __nv_bfloat16* dst = g_Ebf + ((size_t)n * UU + u) * DD;
        #pragma unroll
        for (int j = 0; j < 16; j++) dst[lane + j * 32] = __float2bfloat16(v[j] * inv);
    }
}

// ---------------------------------------------------------------------------
// Kernel C: normalize centroids -> bf16. grid = 64, 256 threads (warp/speaker)
// ---------------------------------------------------------------------------
__global__ void __launch_bounds__(256, 1) cnorm_kernel() {
    const int tid = threadIdx.x, w = tid >> 5, lane = tid & 31;
    const int sp = blockIdx.x * 8 + w;
    float v[16], ss = 0.f;
    #pragma unroll
    for (int j = 0; j < 16; j++) {
        v[j] = g_cent[sp * DD + lane + j * 32];
        ss = fmaf(v[j], v[j], ss);
    }
    #pragma unroll
    for (int o = 16; o > 0; o >>= 1) ss += __shfl_xor_sync(0xffffffffu, ss, o);
    const float inv = 1.0f / fmaxf(sqrtf(ss), EPS);
    #pragma unroll
    for (int j = 0; j < 16; j++)
        g_Cbf[sp * DD + lane + j * 32] = __float2bfloat16(v[j] * inv);
}

// ---------------------------------------------------------------------------
// Kernel G: HMMA GEMM. Block = 64 rows; A (64x512 bf16, 64KB) resident.
// N processed as 8 chunks of 64 speakers, full K per chunk, B double-buffered.
// Online log-softmax per warp-half; halves merged via smem split-softmax.
// grid = 256, 128 threads (4 warps, 2x2 of 32x32 warp tiles).
// ---------------------------------------------------------------------------
#define SM_A   0
#define SM_B(s) (65536 + (s) * 65536)
#define SM_TOT 196608
// smem tile rows are 1KB (512 bf16); swizzle 16B chunk index with row%8
#define SWZ_OFF(r, cb) ((uint32_t)((r) * 1024 + ((((cb)) ^ ((r) & 7)) << 4)))

static __device__ __forceinline__ void load_B_chunk(uint32_t sb, int c, int tid) {
    const uint32_t buf = sb + SM_B(c & 1);
    const __nv_bfloat16* src = g_Cbf + (size_t)c * 64 * DD;
    #pragma unroll
    for (int it = 0; it < 32; it++) {
        const int u = tid + it * 128;
        const int r = u >> 6, cb = u & 63;
        cpa16(buf + SWZ_OFF(r, cb), src + (size_t)r * DD + cb * 8);
    }
    asm volatile("cp.async.commit_group;" ::: "memory");
}

__global__ void __launch_bounds__(128, 1)
gemm_loss_kernel(const float* __restrict__ wp, const float* __restrict__ bp) {
    extern __shared__ char smem[];
    const uint32_t sb = smem_u32(smem);
    const int tid = threadIdx.x, wid = tid >> 5, lane = tid & 31;
    const int bi = blockIdx.x;
    const int wm = wid & 1;        // row half (0/1 -> rows wm*32..)
    const int wn = wid >> 1;       // col half within 64-speaker chunk
    const int l7 = lane & 7;

    // ---- prologue: A + B0 (group 0), then B1 (group 1) ----
    {
        const __nv_bfloat16* As = g_Ebf + (size_t)bi * 64 * DD;
        #pragma unroll
        for (int it = 0; it < 32; it++) {
            const int u = tid + it * 128;
            const int r = u >> 6, cb = u & 63;
            cpa16(sb + SM_A + SWZ_OFF(r, cb), As + (size_t)r * DD + cb * 8);
        }
        const __nv_bfloat16* Bs = g_Cbf;
        #pragma unroll
        for (int it = 0; it < 32; it++) {
            const int u = tid + it * 128;
            const int r = u >> 6, cb = u & 63;
            cpa16(sb + SM_B(0) + SWZ_OFF(r, cb), Bs + (size_t)r * DD + cb * 8);
        }
        asm volatile("cp.async.commit_group;" ::: "memory");
        load_B_chunk(sb, 1, tid);
    }

    // per-thread ldmatrix base addresses
    const uint32_t aoff0 = sb + SM_A + (uint32_t)(wm * 32 + (lane & 15)) * 1024;
    const uint32_t aoff1 = aoff0 + 16 * 1024;
    const int cbA = lane >> 4;          // k-half select for A
    const int cbB = (lane >> 3) & 1;    // k-half select for B
    uint32_t brow[4];
    #pragma unroll
    for (int nt = 0; nt < 4; nt++)
        brow[nt] = (uint32_t)((wn * 32 + nt * 8 + l7) * 1024);

    // diagonal bookkeeping (warp-uniform speaker index)
    const int diag = bi * 2 + wm;          // this warp's rows' speaker
    const int dchunk = diag >> 6;          // which 64-speaker chunk holds it
    const int dwn = (diag >> 5) & 1;       // which warp-column half
    const int dj = diag & 31;              // col within warp tile
    const int dnt = dj >> 3, down = (dj & 7) >> 1, de = dj & 1;

    // online softmax state over THIS WARP'S column half (256 cols)
    float om[4], os[4], od[4];
    #pragma unroll
    for (int i = 0; i < 4; i++) { om[i] = -INFINITY; os[i] = 0.f; od[i] = 0.f; }

    const float Wv = wp[0], Bv = bp[0];

    for (int c = 0; c < 8; c++) {
        if (c < 7) asm volatile("cp.async.wait_group 1;" ::: "memory");
        else       asm volatile("cp.async.wait_group 0;" ::: "memory");
        __syncthreads();

        const uint32_t Bbuf = sb + SM_B(c & 1);
        float acc[2][4][4];
        #pragma unroll
        for (int mt = 0; mt < 2; mt++)
            #pragma unroll
            for (int nt = 0; nt < 4; nt++)
                #pragma unroll
                for (int e = 0; e < 4; e++) acc[mt][nt][e] = 0.f;

        #pragma unroll 8
        for (int kk = 0; kk < 32; kk++) {
            const int cb = kk * 2;
            uint32_t a[2][4];
            ldsm_x4(a[0][0], a[0][1], a[0][2], a[0][3],
                    aoff0 + ((uint32_t)((cb + cbA) ^ l7) << 4));
            ldsm_x4(a[1][0], a[1][1], a[1][2], a[1][3],
                    aoff1 + ((uint32_t)((cb + cbA) ^ l7) << 4));
            uint32_t b[4][2];
            #pragma unroll
            for (int nt = 0; nt < 4; nt++)
                ldsm_x2(b[nt][0], b[nt][1],
                        Bbuf + brow[nt] + ((uint32_t)((cb + cbB) ^ l7) << 4));
            #pragma unroll
            for (int mt = 0; mt < 2; mt++)
                #pragma unroll
                for (int nt = 0; nt < 4; nt++)
                    mma16816(acc[mt][nt][0], acc[mt][nt][1], acc[mt][nt][2], acc[mt][nt][3],
                             a[mt][0], a[mt][1], a[mt][2], a[mt][3], b[nt][0], b[nt][1]);
        }

        // ---- online log-softmax update over this chunk's 8 cols per row ----
        const bool dhit = (c == dchunk) && (wn == dwn) && ((lane & 3) == down);
        #pragma unroll
        for (int mt = 0; mt < 2; mt++) {
            #pragma unroll
            for (int h = 0; h < 2; h++) {
                const int si = mt * 2 + h;
                float v[8], vmax = -INFINITY;
                #pragma unroll
                for (int nt = 0; nt < 4; nt++) {
                    v[nt * 2 + 0] = fmaf(Wv, acc[mt][nt][h * 2 + 0], Bv);
                    v[nt * 2 + 1] = fmaf(Wv, acc[mt][nt][h * 2 + 1], Bv);
                    vmax = fmaxf(vmax, fmaxf(v[nt * 2], v[nt * 2 + 1]));
                }
                const float nm = fmaxf(om[si], vmax);
                float add = 0.f;
                #pragma unroll
                for (int j = 0; j < 8; j++) add += __expf(v[j] - nm);
                os[si] = os[si] * __expf(om[si] - nm) + add;
                om[si] = nm;
                if (dhit) od[si] += v[dnt * 2 + de];
            }
        }

        __syncthreads();
        if (c + 2 < 8) load_B_chunk(sb, c + 2, tid);
    }

    // ---- step 1: combine (m,s,d) across the 4 lanes of each row quad ----
    float fm[4], fs[4], fd[4];
    #pragma unroll
    for (int si = 0; si < 4; si++) {
        float m = om[si], s = os[si], d = od[si];
        #pragma unroll
        for (int off = 1; off <= 2; off <<= 1) {
            const float mo = __shfl_xor_sync(0xffffffffu, m, off);
            const float so = __shfl_xor_sync(0xffffffffu, s, off);
            const float dd = __shfl_xor_sync(0xffffffffu, d, off);
            const float nm = fmaxf(m, mo);
            s = s * __expf(m - nm) + so * __expf(mo - nm);
            m = nm;
            d += dd;
        }
        fm[si] = m; fs[si] = s; fd[si] = d;
    }

    // ---- step 2: merge the two column-half warps (0<->2, 1<->3) via smem ----
    // Each warp's state covers 256 cols; rows are shared between warp wm and wm+2.
    float* sm_m = (float*)smem;          // [4][32]  (A region is dead now)
    float* sm_s = sm_m + 128;            // [4][32]
    float* sm_d = sm_s + 128;            // [4][32]
    __syncthreads();
    if ((lane & 3) == 0) {
        #pragma unroll
        for (int si = 0; si < 4; si++) {
            const int r = (si >> 1) * 16 + (si & 1) * 8 + (lane >> 2); // row in warp
            sm_m[wid * 32 + r] = fm[si];
            sm_s[wid * 32 + r] = fs[si];
            sm_d[wid * 32 + r] = fd[si];
        }
    }
    __syncthreads();

    if (wid < 2) {   // warps 0,1 merge with partners 2,3; row = lane
        const float m0 = sm_m[wid * 32 + lane];
        const float s0 = sm_s[wid * 32 + lane];
        const float d0 = sm_d[wid * 32 + lane];
        const float m1 = sm_m[(wid + 2) * 32 + lane];
        const float s1 = sm_s[(wid + 2) * 32 + lane];
        const float d1 = sm_d[(wid + 2) * 32 + lane];
        const float nm = fmaxf(m0, m1);
        const float s = s0 * __expf(m0 - nm) + s1 * __expf(m1 - nm);
        float local = (d0 + d1) - nm - __logf(s);   // full-row log-prob
        #pragma unroll
        for (int o = 16; o > 0; o >>= 1)
            local += __shfl_xor_sync(0xffffffffu, local, o);
        if (lane == 0) sm_m[384 + wid] = local;
    }
    __syncthreads();
    if (tid == 0) g_part[bi] = sm_m[384] + sm_m[385];
}

// ---------------------------------------------------------------------------
// Kernel F: deterministic final reduction. 256 threads.
// ---------------------------------------------------------------------------
__global__ void finalize_kernel(float* __restrict__ out) {
    __shared__ float red[8];
    const int tid = threadIdx.x;
    float s = g_part[tid];
    #pragma unroll
    for (int o = 16; o > 0; o >>= 1) s += __shfl_xor_sync(0xffffffffu, s, o);
    const int w = tid >> 5, lane = tid & 31;
    if (lane == 0) red[w] = s;
    __syncthreads();
    if (tid == 0) {
        float t = 0.f;
        #pragma unroll
        for (int i = 0; i < 8; i++) t += red[i];
        out[0] = -t * (1.0f / (float)NU);
    }
}

extern "C" void kernel_launch(void* const* d_in, const int* in_sizes, int n_in,
                              void* d_out, int out_size) {
    const float* emb = (const float*)d_in[0];
    const float* w = (const float*)d_in[1];
    const float* b = (const float*)d_in[2];
    float* out = (float*)d_out;

    cudaFuncSetAttribute(prep_kernel, cudaFuncAttributeMaxDynamicSharedMemorySize, 65536);
    cudaFuncSetAttribute(gemm_loss_kernel, cudaFuncAttributeMaxDynamicSharedMemorySize, SM_TOT);

    prep_kernel<<<NSPK, 256, 65536>>>(emb);
    cnorm_kernel<<<64, 256>>>();
    gemm_loss_kernel<<<256, 128, SM_TOT>>>(w, b);
    finalize_kernel<<<1, 256>>>(out);
}